// round 4
// baseline (speedup 1.0000x reference)
#include <cuda_runtime.h>
#include <math.h>

// Problem constants
#define LSEQ   8192
#define NBATCH 1024
#define NT     512       // threads per FFT block
#define NSTATE 64

#define PI_D 3.14159265358979323846

// Scratch (no allocations allowed -> __device__ globals)
__device__ float2 g_wm[16384];   // WM[k] = exp(-2*pi*i*k/16384)
__device__ float2 g_kh[4100];    // K_hat spectrum (L-point rfft bins 0..4096)
__device__ float2 g_kf[8200];    // rfft_16384 of zero-padded K, bins 0..8192

// ---------------- complex helpers ----------------
static __device__ __forceinline__ float2 cmul(float2 a, float2 b) {
    return make_float2(a.x*b.x - a.y*b.y, a.x*b.y + a.y*b.x);
}
static __device__ __forceinline__ float2 cadd(float2 a, float2 b){ return make_float2(a.x+b.x, a.y+b.y); }
static __device__ __forceinline__ float2 csub(float2 a, float2 b){ return make_float2(a.x-b.x, a.y-b.y); }
static __device__ __forceinline__ float2 cconj(float2 a){ return make_float2(a.x, -a.y); }
static __device__ __forceinline__ float2 cscale(float2 a, float s){ return make_float2(a.x*s, a.y*s); }

// ---------------- twiddle table ----------------
__global__ void init_twiddle_kernel() {
    int k = blockIdx.x * blockDim.x + threadIdx.x;
    if (k < 16384) {
        double a = (2.0 * PI_D / 16384.0) * (double)k;
        double s, c;
        sincos(a, &s, &c);
        g_wm[k] = make_float2((float)c, (float)(-s));
    }
}

// ---------------- Cauchy kernel: K_hat[f], f = 0..4096 (fp64) ----------------
__global__ void khat_kernel(const float* __restrict__ Bv, const float* __restrict__ Cv) {
    int f = blockIdx.x * blockDim.x + threadIdx.x;
    if (f > 4096) return;
    double th = (2.0 * PI_D / 8192.0) * (double)f;
    double s, c;
    sincos(th, &s, &c);                 // omega = c + i s
    double nr = 1.0 - c, ni = -s;       // 1 - omega
    double dr = 1.0 + c, di = s;        // 1 + omega
    double dd = dr*dr + di*di;
    double gr = 20.0 * (nr*dr + ni*di) / dd;   // g = (2/dt)*(1-w)/(1+w), dt=0.1
    double gi = 20.0 * (ni*dr - nr*di) / dd;

    double k00r=0,k00i=0,k01r=0,k01i=0,k10r=0,k10i=0,k11r=0,k11i=0;
    #pragma unroll 8
    for (int n = 0; n < NSTATE; n++) {
        double er = gr + 0.5;                  // g - (-0.5)
        double ei = gi - PI_D * (double)n;     // g - i*pi*n
        double e2 = er*er + ei*ei;
        double ir =  er / e2, ii = -ei / e2;   // inv = 1/(g - Lambda)
        double b0 = (double)Bv[n];
        double a0 = (double)Cv[n];
        double p  = sqrt((double)n + 0.5);     // P = Q (real)
        double w;
        w = a0*b0; k00r += w*ir; k00i += w*ii;
        w = a0*p;  k01r += w*ir; k01i += w*ii;
        w = p*b0;  k10r += w*ir; k10i += w*ii;
        w = p*p;   k11r += w*ir; k11i += w*ii;
    }
    // t = k01 * (1 + k11) * k10
    double ur = 1.0 + k11r, ui = k11i;
    double t1r = k01r*ur - k01i*ui, t1i = k01r*ui + k01i*ur;
    double t2r = t1r*k10r - t1i*k10i, t2i = t1r*k10i + t1i*k10r;
    double hr = k00r - t2r, hi = k00i - t2i;
    // c2 = 2/(1+omega)
    double c2r = 2.0*dr/dd, c2i = -2.0*di/dd;
    double Kr = c2r*hr - c2i*hi, Ki = c2r*hi + c2i*hr;
    g_kh[f] = make_float2((float)Kr, (float)Ki);
}

// ---------------- radix-4 Stockham FFT, N=8192, forward (sign -1) ----------------
// Reads A, ping-pongs A<->B across 7 stages (6x radix-4 + 1x radix-2).
// Result lands in B. Includes trailing __syncthreads().
static __device__ __forceinline__ void fft8192(float2* A, float2* B, int tid) {
    float2* src = A;
    float2* dst = B;
    #pragma unroll
    for (int st = 0; st < 6; st++) {
        const int ls    = 2 * st;                 // log2(s): 0,2,4,6,8,10
        const int s     = 1 << ls;                // 1,4,16,64,256,1024
        const int tstep = 2 << (2 * st);          // 2*s: twiddle idx = p*2s  (FIXED)
        #pragma unroll
        for (int it = 0; it < 4; it++) {
            int idx = tid + it * NT;              // idx = p*s + q, idx < 2048
            int p = idx >> ls;
            int q = idx & (s - 1);
            float2 a = src[idx];
            float2 b = src[idx + 2048];
            float2 c = src[idx + 4096];
            float2 d = src[idx + 6144];
            float2 apc = cadd(a, c), amc = csub(a, c);
            float2 bpd = cadd(b, d), bmd = csub(b, d);
            float2 jb  = make_float2(-bmd.y, bmd.x);   // i*(b-d)
            float2 w1 = g_wm[p * tstep];               // exp(-2*pi*i*p/(8192/s))
            float2 w2 = cmul(w1, w1);
            float2 w3 = cmul(w2, w1);
            int o = q + (p << (ls + 2));               // q + 4*s*p
            dst[o]         = cadd(apc, bpd);
            dst[o + s]     = cmul(w1, csub(amc, jb));
            dst[o + 2 * s] = cmul(w2, csub(apc, bpd));
            dst[o + 3 * s] = cmul(w3, cadd(amc, jb));
        }
        __syncthreads();
        float2* t = src; src = dst; dst = t;
    }
    // after 6 swaps: src == A, dst == B. Final radix-2 stage, s = 4096.
    #pragma unroll
    for (int it = 0; it < 8; it++) {
        int q = tid + it * NT;
        float2 a = src[q], b = src[q + 4096];
        dst[q]        = cadd(a, b);
        dst[q + 4096] = csub(a, b);
    }
    __syncthreads();
}

// ---------------- K preparation: irfft_8192(K_hat) -> K -> rfft_16384(K_pad) ----------------
__global__ void kprep_kernel() {
    extern __shared__ float2 sm[];
    float2* A = sm;
    float2* B = sm + 8192;
    int tid = threadIdx.x;

    // Hermitian-extend K_hat and conjugate (conj trick for inverse FFT)
    #pragma unroll
    for (int it = 0; it < 16; it++) {
        int f = tid + it * NT;
        float2 kh = (f <= 4096) ? g_kh[f] : g_kh[8192 - f];
        A[f] = (f <= 4096) ? cconj(kh) : kh;
    }
    __syncthreads();
    fft8192(A, B, tid);
    // K[t] = Re(conj(B[t]))/8192 = B[t].x/8192 ; pack K_pad (16384, zeros beyond 8192)
    const float sc = 1.0f / 8192.0f;
    #pragma unroll
    for (int it = 0; it < 16; it++) {
        int j = tid + it * NT;
        A[j] = (j < 4096) ? make_float2(B[2*j].x * sc, B[2*j + 1].x * sc)
                          : make_float2(0.f, 0.f);
    }
    __syncthreads();
    fft8192(A, B, tid);
    // Unpack to rfft_16384 bins 0..8192
    for (int k = tid; k <= 4096; k += NT) {
        if (k == 0) {
            float2 Z0 = B[0];
            g_kf[0]    = make_float2(Z0.x + Z0.y, 0.f);
            g_kf[8192] = make_float2(Z0.x - Z0.y, 0.f);
        } else {
            int hk = 8192 - k;
            float2 Zk  = B[k];
            float2 Zhc = cconj(B[hk]);
            float2 E  = cscale(cadd(Zk, Zhc), 0.5f);
            float2 Om = csub(Zk, Zhc);
            float2 O  = make_float2(0.5f * Om.y, -0.5f * Om.x);   // -i/2 * (Zk - Zhc)
            float2 w  = g_wm[k];
            g_kf[k] = cadd(E, cmul(w, O));
            if (k != 4096) {
                float2 wh = make_float2(-w.x, w.y);               // -conj(w) = WM[hk]
                g_kf[hk] = cadd(cconj(E), cmul(wh, cconj(O)));
            }
        }
    }
}

// ---------------- main batched FFT convolution ----------------
__global__ void __launch_bounds__(NT, 1) conv_kernel(const float* __restrict__ x,
                                                     float* __restrict__ y) {
    extern __shared__ float2 sm[];
    float2* A = sm;
    float2* B = sm + 8192;
    int b = blockIdx.x;
    int tid = threadIdx.x;

    // pack two reals per complex: z[j] = x[2j] + i*x[2j+1]; zero pad upper half
    const float2* xr = (const float2*)(x + (size_t)b * LSEQ);
    #pragma unroll
    for (int it = 0; it < 16; it++) {
        int j = tid + it * NT;
        A[j] = (j < 4096) ? xr[j] : make_float2(0.f, 0.f);
    }
    __syncthreads();

    fft8192(A, B, tid);   // Z in B

    // unpack -> multiply by Kf -> repack (writes conj(Zy) into A for conj-trick IFFT)
    for (int k = tid; k <= 4096; k += NT) {
        if (k == 0) {
            float2 Z0 = B[0];
            float X0 = Z0.x + Z0.y;
            float XH = Z0.x - Z0.y;
            float2 Y0 = cscale(g_kf[0], X0);
            float2 YH = cscale(g_kf[8192], XH);
            float2 Yhc = cconj(YH);
            float2 S = cscale(cadd(Y0, Yhc), 0.5f);
            float2 D = cscale(csub(Y0, Yhc), 0.5f);
            float2 Zy0 = make_float2(S.x - D.y, S.y + D.x);       // S + i*D
            A[0] = cconj(Zy0);
        } else {
            int hk = 8192 - k;
            float2 Zk  = B[k];
            float2 Zhc = cconj(B[hk]);
            float2 E  = cscale(cadd(Zk, Zhc), 0.5f);
            float2 Om = csub(Zk, Zhc);
            float2 O  = make_float2(0.5f * Om.y, -0.5f * Om.x);
            float2 w  = g_wm[k];                                  // exp(-2*pi*i*k/16384)
            float2 Xk = cadd(E, cmul(w, O));
            float2 wh = make_float2(-w.x, w.y);                   // WM[hk] = -conj(w)
            float2 Xh = cadd(cconj(E), cmul(wh, cconj(O)));
            float2 Yk = cmul(Xk, g_kf[k]);
            float2 Yh = cmul(Xh, g_kf[hk]);
            // Zy[k] = (Yk + conj(Yh))/2 + i*conj(w)*(Yk - conj(Yh))/2
            float2 Yhc = cconj(Yh);
            float2 S = cscale(cadd(Yk, Yhc), 0.5f);
            float2 D = cscale(csub(Yk, Yhc), 0.5f);
            float2 u = cmul(cconj(w), D);
            float2 Zyk = make_float2(S.x - u.y, S.y + u.x);
            A[k] = cconj(Zyk);
            if (k != 4096) {
                // Zy[hk] = (Yh + conj(Yk))/2 - i*w*(Yh - conj(Yk))/2   (w^{-hk} = -w^k)
                float2 Ykc = cconj(Yk);
                float2 S2 = cscale(cadd(Yh, Ykc), 0.5f);
                float2 D2 = cscale(csub(Yh, Ykc), 0.5f);
                float2 v = cmul(w, D2);
                float2 Zyh = make_float2(S2.x + v.y, S2.y - v.x); // S2 - i*v
                A[hk] = cconj(Zyh);
            }
        }
    }
    __syncthreads();

    fft8192(A, B, tid);   // F in B; zy[j] = conj(F[j]) / 8192

    // y[2j] = F.x/8192, y[2j+1] = -F.y/8192 ; only first LSEQ outputs needed (j < 4096)
    float2* yr = (float2*)(y + (size_t)b * LSEQ);
    const float sc = 1.0f / 8192.0f;
    #pragma unroll
    for (int it = 0; it < 8; it++) {
        int j = tid + it * NT;
        float2 f = B[j];
        yr[j] = make_float2(f.x * sc, -f.y * sc);
    }
}

// ---------------- launch ----------------
extern "C" void kernel_launch(void* const* d_in, const int* in_sizes, int n_in,
                              void* d_out, int out_size) {
    const float* x  = (const float*)d_in[0];
    const float* Bv = (const float*)d_in[1];
    const float* Cv = (const float*)d_in[2];
    float* y = (float*)d_out;
    (void)in_sizes; (void)n_in; (void)out_size;

    const int smem = 2 * 8192 * (int)sizeof(float2);   // 131072 B
    cudaFuncSetAttribute(kprep_kernel, cudaFuncAttributeMaxDynamicSharedMemorySize, smem);
    cudaFuncSetAttribute(conv_kernel,  cudaFuncAttributeMaxDynamicSharedMemorySize, smem);

    init_twiddle_kernel<<<64, 256>>>();
    khat_kernel<<<17, 256>>>(Bv, Cv);
    kprep_kernel<<<1, NT, smem>>>();
    conv_kernel<<<NBATCH, NT, smem>>>(x, y);
}

// round 6
// speedup vs baseline: 3.1381x; 3.1381x over previous
#include <cuda_runtime.h>
#include <math.h>

#define LSEQ   8192
#define NBATCH 1024
#define NT     512
#define NSTATE 64
#define PI_D 3.14159265358979323846

__device__ float2 g_wm[16384];   // WM[k] = exp(-2*pi*i*k/16384)
__device__ float2 g_kh[4100];    // K_hat spectrum bins 0..4096
__device__ float2 g_kf[8200];    // rfft_16384 of padded K, bins 0..8192

// ---------------- complex helpers ----------------
static __device__ __forceinline__ float2 cmul(float2 a, float2 b) {
    return make_float2(a.x*b.x - a.y*b.y, a.x*b.y + a.y*b.x);
}
static __device__ __forceinline__ float2 cadd(float2 a, float2 b){ return make_float2(a.x+b.x, a.y+b.y); }
static __device__ __forceinline__ float2 csub(float2 a, float2 b){ return make_float2(a.x-b.x, a.y-b.y); }
static __device__ __forceinline__ float2 cconj(float2 a){ return make_float2(a.x, -a.y); }
static __device__ __forceinline__ float2 cscale(float2 a, float s){ return make_float2(a.x*s, a.y*s); }

// ---------------- twiddle table ----------------
__global__ void init_twiddle_kernel() {
    int k = blockIdx.x * blockDim.x + threadIdx.x;
    if (k < 16384) {
        double s, c;
        sincospi((double)k / 8192.0, &s, &c);   // angle = 2*pi*k/16384
        g_wm[k] = make_float2((float)c, (float)(-s));
    }
}

// ---------------- Cauchy kernel: one block per frequency f ----------------
// NOTE: must use sincos (NOT sincospi): at f=4096 sincospi gives exactly
// (s=0, c=-1) -> 1+omega == 0 -> 0/0 NaN. sincos(pi_double) gives
// s ~ 1.22e-16 != 0, keeping the Nyquist bin finite (matches reference's
// own f32 cancellation; contribution is negligible after irfft).
__global__ void khat_kernel(const float* __restrict__ Bv, const float* __restrict__ Cv) {
    __shared__ double shg[5];        // gr, gi, dr, di, dd
    __shared__ double wsum[2][8];
    int f = blockIdx.x;              // 0..4096
    int n = threadIdx.x;             // 0..63
    if (n == 0) {
        double th = (2.0 * PI_D / 8192.0) * (double)f;
        double s, c;
        sincos(th, &s, &c);          // omega = c + i s
        double nr = 1.0 - c, ni = -s;
        double dr = 1.0 + c, di = s;
        double dd = dr*dr + di*di;
        shg[0] = 20.0 * (nr*dr + ni*di) / dd;
        shg[1] = 20.0 * (ni*dr - nr*di) / dd;
        shg[2] = dr; shg[3] = di; shg[4] = dd;
    }
    __syncthreads();
    double gr = shg[0], gi = shg[1];
    double er = gr + 0.5;
    double ei = gi - PI_D * (double)n;
    double inv = 1.0 / (er*er + ei*ei);
    double ir =  er * inv, ii = -ei * inv;
    double b0 = (double)Bv[n];
    double a0 = (double)Cv[n];
    double p2 = (double)n + 0.5;
    double p  = sqrt(p2);
    double v00 = a0*b0, v01 = a0*p, v10 = p*b0, v11 = p2;
    double acc[8] = { v00*ir, v00*ii, v01*ir, v01*ii,
                      v10*ir, v10*ii, v11*ir, v11*ii };
    #pragma unroll
    for (int off = 16; off; off >>= 1) {
        #pragma unroll
        for (int t = 0; t < 8; t++)
            acc[t] += __shfl_down_sync(0xffffffffu, acc[t], off);
    }
    if ((n & 31) == 0) {
        #pragma unroll
        for (int t = 0; t < 8; t++) wsum[n >> 5][t] = acc[t];
    }
    __syncthreads();
    if (n == 0) {
        double k00r = wsum[0][0]+wsum[1][0], k00i = wsum[0][1]+wsum[1][1];
        double k01r = wsum[0][2]+wsum[1][2], k01i = wsum[0][3]+wsum[1][3];
        double k10r = wsum[0][4]+wsum[1][4], k10i = wsum[0][5]+wsum[1][5];
        double k11r = wsum[0][6]+wsum[1][6], k11i = wsum[0][7]+wsum[1][7];
        double ur = 1.0 + k11r, ui = k11i;
        double t1r = k01r*ur - k01i*ui, t1i = k01r*ui + k01i*ur;
        double t2r = t1r*k10r - t1i*k10i, t2i = t1r*k10i + t1i*k10r;
        double hr = k00r - t2r, hi = k00i - t2i;
        double dr = shg[2], di = shg[3], dd = shg[4];
        double c2r = 2.0*dr/dd, c2i = -2.0*di/dd;
        g_kh[f] = make_float2((float)(c2r*hr - c2i*hi), (float)(c2r*hi + c2i*hr));
    }
}

// ---------------- radix-8 Stockham FFT, N=8192, forward ----------------
// 4 radix-8 stages + final radix-2. Reads A, result in B (trailing sync).
// ZHI: input's upper half (idx>=4096) is known zero (skip loads).
// SKIPHI: skip storing outputs [4096,8192) of the final stage.
template<int NTH, bool ZHI, bool SKIPHI>
static __device__ __forceinline__ void fft8192_r8(float2* A, float2* B, int tid) {
    float2* src = A;
    float2* dst = B;
    #pragma unroll
    for (int st = 0; st < 4; st++) {
        const int ls = 3 * st;            // log2(s): 0,3,6,9
        const int s  = 1 << ls;           // 1,8,64,512
        #pragma unroll
        for (int it = 0; it < 1024 / NTH; it++) {
            int idx = tid + it * NTH;     // < 1024
            int p = idx >> ls;
            int q = idx & (s - 1);
            float2 x0 = src[idx];
            float2 x1 = src[idx + 1024];
            float2 x2 = src[idx + 2048];
            float2 x3 = src[idx + 3072];
            float2 x4, x5, x6, x7;
            if (ZHI && st == 0) {
                x4 = x5 = x6 = x7 = make_float2(0.f, 0.f);
            } else {
                x4 = src[idx + 4096];
                x5 = src[idx + 5120];
                x6 = src[idx + 6144];
                x7 = src[idx + 7168];
            }
            // E = DFT4(x0,x2,x4,x6), O = DFT4(x1,x3,x5,x7)
            float2 ea = cadd(x0, x4), em = csub(x0, x4);
            float2 eb = cadd(x2, x6), en = csub(x2, x6);
            float2 ej = make_float2(-en.y, en.x);
            float2 E0 = cadd(ea, eb), E1 = csub(em, ej);
            float2 E2 = csub(ea, eb), E3 = cadd(em, ej);
            float2 oa = cadd(x1, x5), om = csub(x1, x5);
            float2 ob = cadd(x3, x7), on = csub(x3, x7);
            float2 oj = make_float2(-on.y, on.x);
            float2 O0 = cadd(oa, ob), O1 = csub(om, oj);
            float2 O2 = csub(oa, ob), O3 = cadd(om, oj);
            const float C = 0.70710678118654752440f;
            float2 t0 = O0;
            float2 t1 = make_float2(C*(O1.x + O1.y), C*(O1.y - O1.x));   // w8^1 * O1
            float2 t2 = make_float2(O2.y, -O2.x);                         // -i * O2
            float2 t3 = make_float2(C*(O3.y - O3.x), -C*(O3.x + O3.y));   // w8^3 * O3
            float2 X0 = cadd(E0, t0), X4 = csub(E0, t0);
            float2 X1 = cadd(E1, t1), X5 = csub(E1, t1);
            float2 X2 = cadd(E2, t2), X6 = csub(E2, t2);
            float2 X3 = cadd(E3, t3), X7 = csub(E3, t3);
            // twiddles: w_j = exp(-2*pi*i * p*s*j / 8192) = g_wm[2*p*s*j]
            int tw = (p << (ls + 1));       // 2*p*s  (<= 2046)
            float2 w1 = g_wm[tw];
            float2 w2 = cmul(w1, w1);
            float2 w3 = cmul(w2, w1);
            float2 w4 = cmul(w2, w2);
            float2 w5 = cmul(w3, w2);
            float2 w6 = cmul(w3, w3);
            float2 w7 = cmul(w4, w3);
            int o = q + (p << (ls + 3));    // q + 8*s*p
            dst[o]         = X0;
            dst[o + s]     = cmul(w1, X1);
            dst[o + 2*s]   = cmul(w2, X2);
            dst[o + 3*s]   = cmul(w3, X3);
            dst[o + 4*s]   = cmul(w4, X4);
            dst[o + 5*s]   = cmul(w5, X5);
            dst[o + 6*s]   = cmul(w6, X6);
            dst[o + 7*s]   = cmul(w7, X7);
        }
        __syncthreads();
        float2* t = src; src = dst; dst = t;
    }
    // After 4 swaps: src == A, dst == B. Final radix-2 (s=4096, p=0 -> no twiddle).
    #pragma unroll
    for (int it = 0; it < 4096 / NTH; it++) {
        int q = tid + it * NTH;
        float2 a = src[q], b = src[q + 4096];
        dst[q] = cadd(a, b);
        if (!SKIPHI) dst[q + 4096] = csub(a, b);
    }
    __syncthreads();
}

// ---------------- K preparation ----------------
__global__ void kprep_kernel() {
    extern __shared__ float2 sm[];
    float2* A = sm;
    float2* B = sm + 8192;
    int tid = threadIdx.x;

    // Hermitian-extend K_hat and conjugate (conj trick for inverse FFT)
    #pragma unroll
    for (int it = 0; it < 16; it++) {
        int f = tid + it * NT;
        float2 kh = (f <= 4096) ? g_kh[f] : g_kh[8192 - f];
        A[f] = (f <= 4096) ? cconj(kh) : kh;
    }
    __syncthreads();
    fft8192_r8<NT, false, false>(A, B, tid);
    // K[t] = B[t].x/8192 ; pack K_pad halves (upper half zero -> ZHI on next FFT)
    const float sc = 1.0f / 8192.0f;
    #pragma unroll
    for (int it = 0; it < 8; it++) {
        int j = tid + it * NT;   // j < 4096
        A[j] = make_float2(B[2*j].x * sc, B[2*j + 1].x * sc);
    }
    __syncthreads();
    fft8192_r8<NT, true, false>(A, B, tid);
    // Unpack to rfft_16384 bins 0..8192
    for (int k = tid; k <= 4096; k += NT) {
        if (k == 0) {
            float2 Z0 = B[0];
            g_kf[0]    = make_float2(Z0.x + Z0.y, 0.f);
            g_kf[8192] = make_float2(Z0.x - Z0.y, 0.f);
        } else {
            int hk = 8192 - k;
            float2 Zk  = B[k];
            float2 Zhc = cconj(B[hk]);
            float2 E  = cscale(cadd(Zk, Zhc), 0.5f);
            float2 Om = csub(Zk, Zhc);
            float2 O  = make_float2(0.5f * Om.y, -0.5f * Om.x);
            float2 w  = g_wm[k];
            g_kf[k] = cadd(E, cmul(w, O));
            if (k != 4096) {
                float2 wh = make_float2(-w.x, w.y);
                g_kf[hk] = cadd(cconj(E), cmul(wh, cconj(O)));
            }
        }
    }
}

// ---------------- main batched FFT convolution ----------------
__global__ void __launch_bounds__(NT, 1) conv_kernel(const float* __restrict__ x,
                                                     float* __restrict__ y) {
    extern __shared__ float2 sm[];
    float2* A = sm;
    float2* B = sm + 8192;
    int b = blockIdx.x;
    int tid = threadIdx.x;

    // pack two reals per complex; upper half stays unwritten (ZHI FFT skips it)
    const float2* xr = (const float2*)(x + (size_t)b * LSEQ);
    #pragma unroll
    for (int it = 0; it < 8; it++) {
        int j = tid + it * NT;   // j < 4096
        A[j] = xr[j];
    }
    __syncthreads();

    fft8192_r8<NT, true, false>(A, B, tid);   // Z in B

    // unpack -> multiply by Kf -> repack conj(Zy) into A
    for (int k = tid; k <= 4096; k += NT) {
        if (k == 0) {
            float2 Z0 = B[0];
            float X0 = Z0.x + Z0.y;
            float XH = Z0.x - Z0.y;
            float2 Y0 = cscale(g_kf[0], X0);
            float2 YH = cscale(g_kf[8192], XH);
            float2 Yhc = cconj(YH);
            float2 S = cscale(cadd(Y0, Yhc), 0.5f);
            float2 D = cscale(csub(Y0, Yhc), 0.5f);
            float2 Zy0 = make_float2(S.x - D.y, S.y + D.x);
            A[0] = cconj(Zy0);
        } else {
            int hk = 8192 - k;
            float2 Zk  = B[k];
            float2 Zhc = cconj(B[hk]);
            float2 E  = cscale(cadd(Zk, Zhc), 0.5f);
            float2 Om = csub(Zk, Zhc);
            float2 O  = make_float2(0.5f * Om.y, -0.5f * Om.x);
            float2 w  = g_wm[k];
            float2 Xk = cadd(E, cmul(w, O));
            float2 wh = make_float2(-w.x, w.y);
            float2 Xh = cadd(cconj(E), cmul(wh, cconj(O)));
            float2 Yk = cmul(Xk, g_kf[k]);
            float2 Yh = cmul(Xh, g_kf[hk]);
            float2 Yhc = cconj(Yh);
            float2 S = cscale(cadd(Yk, Yhc), 0.5f);
            float2 D = cscale(csub(Yk, Yhc), 0.5f);
            float2 u = cmul(cconj(w), D);
            float2 Zyk = make_float2(S.x - u.y, S.y + u.x);
            A[k] = cconj(Zyk);
            if (k != 4096) {
                float2 Ykc = cconj(Yk);
                float2 S2 = cscale(cadd(Yh, Ykc), 0.5f);
                float2 D2 = cscale(csub(Yh, Ykc), 0.5f);
                float2 v = cmul(w, D2);
                float2 Zyh = make_float2(S2.x + v.y, S2.y - v.x);
                A[hk] = cconj(Zyh);
            }
        }
    }
    __syncthreads();

    fft8192_r8<NT, false, true>(A, B, tid);   // only low half of F needed

    float2* yr = (float2*)(y + (size_t)b * LSEQ);
    const float sc = 1.0f / 8192.0f;
    #pragma unroll
    for (int it = 0; it < 8; it++) {
        int j = tid + it * NT;
        float2 f = B[j];
        yr[j] = make_float2(f.x * sc, -f.y * sc);
    }
}

// ---------------- launch ----------------
extern "C" void kernel_launch(void* const* d_in, const int* in_sizes, int n_in,
                              void* d_out, int out_size) {
    const float* x  = (const float*)d_in[0];
    const float* Bv = (const float*)d_in[1];
    const float* Cv = (const float*)d_in[2];
    float* y = (float*)d_out;
    (void)in_sizes; (void)n_in; (void)out_size;

    const int smem = 2 * 8192 * (int)sizeof(float2);   // 131072 B
    cudaFuncSetAttribute(kprep_kernel, cudaFuncAttributeMaxDynamicSharedMemorySize, smem);
    cudaFuncSetAttribute(conv_kernel,  cudaFuncAttributeMaxDynamicSharedMemorySize, smem);

    init_twiddle_kernel<<<64, 256>>>();
    khat_kernel<<<4097, 64>>>(Bv, Cv);
    kprep_kernel<<<1, NT, smem>>>();
    conv_kernel<<<NBATCH, NT, smem>>>(x, y);
}